// round 2
// baseline (speedup 1.0000x reference)
#include <cuda_runtime.h>
#include <cuda_bf16.h>
#include <math.h>

#define NN 50000
#define DD 128
#define KK 32
#define TWO_D 256

// Scratch for wq = [v_fea | t_emb] @ W.T   [N, 2D]
__device__ float g_wq[(size_t)NN * TWO_D];

// ---------------------------------------------------------------------------
// Kernel 1: wq[m][j] = sum_k q[m][k] * W[j][k],  q = [v_fea | t_emb]
// fp32 tiled GEMM: BM=128, BN=128, BK=32, 256 threads, 8x8 per thread
// ---------------------------------------------------------------------------
#define BM 128
#define BN 128
#define BK 32

__global__ __launch_bounds__(256) void wq_gemm(const float* __restrict__ v_fea,
                                               const float* __restrict__ t_emb,
                                               const float* __restrict__ W) {
    __shared__ float As[BK][BM + 4];
    __shared__ float Bs[BK][BN + 4];

    const int m0 = blockIdx.x * BM;
    const int j0 = blockIdx.y * BN;
    const int tid = threadIdx.x;
    const int tm = (tid >> 4) * 8;   // 16 row-groups
    const int tn = (tid & 15) * 8;   // 16 col-groups

    float acc[8][8];
#pragma unroll
    for (int i = 0; i < 8; i++)
#pragma unroll
        for (int j = 0; j < 8; j++) acc[i][j] = 0.f;

    for (int k0 = 0; k0 < TWO_D; k0 += BK) {
        // chunk lies fully in v_fea (k0<128) or t_emb (k0>=128)
        const float* src = (k0 < DD) ? (v_fea + k0) : (t_emb + (k0 - DD));

        // load A tile: 128 rows x 32 k  (transposed into As[k][m])
#pragma unroll
        for (int i = 0; i < 4; i++) {
            int idx = tid + i * 256;
            int mm = idx >> 3;
            int kq = (idx & 7) * 4;
            int m = m0 + mm;
            float4 val = make_float4(0.f, 0.f, 0.f, 0.f);
            if (m < NN) val = *(const float4*)(src + (size_t)m * DD + kq);
            As[kq + 0][mm] = val.x;
            As[kq + 1][mm] = val.y;
            As[kq + 2][mm] = val.z;
            As[kq + 3][mm] = val.w;
        }
        // load B tile: W[j0+jj][k0+kq..]  (transposed into Bs[k][j])
#pragma unroll
        for (int i = 0; i < 4; i++) {
            int idx = tid + i * 256;
            int jj = idx >> 3;
            int kq = (idx & 7) * 4;
            float4 val = *(const float4*)(W + (size_t)(j0 + jj) * TWO_D + k0 + kq);
            Bs[kq + 0][jj] = val.x;
            Bs[kq + 1][jj] = val.y;
            Bs[kq + 2][jj] = val.z;
            Bs[kq + 3][jj] = val.w;
        }
        __syncthreads();

#pragma unroll
        for (int kk = 0; kk < BK; kk++) {
            float a[8], b[8];
            *(float4*)(a)     = *(const float4*)&As[kk][tm];
            *(float4*)(a + 4) = *(const float4*)&As[kk][tm + 4];
            *(float4*)(b)     = *(const float4*)&Bs[kk][tn];
            *(float4*)(b + 4) = *(const float4*)&Bs[kk][tn + 4];
#pragma unroll
            for (int i = 0; i < 8; i++)
#pragma unroll
                for (int j = 0; j < 8; j++) acc[i][j] = fmaf(a[i], b[j], acc[i][j]);
        }
        __syncthreads();
    }

#pragma unroll
    for (int i = 0; i < 8; i++) {
        int m = m0 + tm + i;
        if (m < NN) {
            float* dst = g_wq + (size_t)m * TWO_D + j0 + tn;
            *(float4*)(dst)     = make_float4(acc[i][0], acc[i][1], acc[i][2], acc[i][3]);
            *(float4*)(dst + 4) = make_float4(acc[i][4], acc[i][5], acc[i][6], acc[i][7]);
        }
    }
}

// ---------------------------------------------------------------------------
// Kernel 2: per-node edge attention with online softmax.
// One warp per node; lanes span D (4 floats/lane). Each neighbor's v/t row
// is gathered ONCE (coalesced 512B loads); scores via warp butterfly reduce.
// ---------------------------------------------------------------------------
__global__ __launch_bounds__(256) void edge_attn(const float* __restrict__ v_fea,
                                                 const float* __restrict__ t_emb,
                                                 const int* __restrict__ ef,
                                                 float* __restrict__ out) {
    const int warp = (blockIdx.x * blockDim.x + threadIdx.x) >> 5;
    const int lane = threadIdx.x & 31;
    if (warp >= NN) return;

    const float* wqr = g_wq + (size_t)warp * TWO_D;
    const float4 wqa = *(const float4*)(wqr + lane * 4);        // wq[0:128] slice
    const float4 wqb = *(const float4*)(wqr + DD + lane * 4);   // wq[128:256] slice

    // each lane holds one neighbor index; broadcast per-k
    const int e_mine = ef[(size_t)warp * KK + lane];

    float m = -INFINITY;
    float s = 0.f;
    float4 acc = make_float4(0.f, 0.f, 0.f, 0.f);

#pragma unroll 4
    for (int k = 0; k < KK; k++) {
        int e = __shfl_sync(0xffffffffu, e_mine, k);
        const float4 v = *(const float4*)(v_fea + (size_t)e * DD + lane * 4);
        const float4 t = *(const float4*)(t_emb + (size_t)e * DD + lane * 4);

        float p = v.x * wqa.x + v.y * wqa.y + v.z * wqa.z + v.w * wqa.w
                + t.x * wqb.x + t.y * wqb.y + t.z * wqb.z + t.w * wqb.w;
        // butterfly reduce -> all lanes get full dot product
        p += __shfl_xor_sync(0xffffffffu, p, 16);
        p += __shfl_xor_sync(0xffffffffu, p, 8);
        p += __shfl_xor_sync(0xffffffffu, p, 4);
        p += __shfl_xor_sync(0xffffffffu, p, 2);
        p += __shfl_xor_sync(0xffffffffu, p, 1);

        // online softmax update
        float mn = fmaxf(m, p);
        float c = __expf(m - mn);   // m=-inf first iter -> c=0
        float w = __expf(p - mn);
        s = s * c + w;
        acc.x = acc.x * c + w * v.x;
        acc.y = acc.y * c + w * v.y;
        acc.z = acc.z * c + w * v.z;
        acc.w = acc.w * c + w * v.w;
        m = mn;
    }

    const float inv = 1.f / s;
    float4 o = make_float4(acc.x * inv, acc.y * inv, acc.z * inv, acc.w * inv);
    *(float4*)(out + (size_t)warp * DD + lane * 4) = o;
}

// ---------------------------------------------------------------------------
extern "C" void kernel_launch(void* const* d_in, const int* in_sizes, int n_in,
                              void* d_out, int out_size) {
    const float* v_fea = (const float*)d_in[0];
    const float* t_emb = (const float*)d_in[1];
    const int* ef = (const int*)d_in[2];
    const float* W = (const float*)d_in[3];
    float* out = (float*)d_out;

    dim3 g1((NN + BM - 1) / BM, TWO_D / BN);
    wq_gemm<<<g1, 256>>>(v_fea, t_emb, W);

    int warps_per_block = 256 / 32;
    int grid2 = (NN + warps_per_block - 1) / warps_per_block;
    edge_attn<<<grid2, 256>>>(v_fea, t_emb, ef, out);
}

// round 4
// speedup vs baseline: 1.2794x; 1.2794x over previous
#include <cuda_runtime.h>
#include <cuda_bf16.h>
#include <math.h>
#include <stdint.h>

#define NN 50000
#define MP 50048          // NN padded to 128
#define DD 128
#define KK 32
#define TWO_D 256
#define KP 768            // 3 * 256 (hi|lo|hi concat K)

// ---------------------------------------------------------------------------
// Global scratch
// ---------------------------------------------------------------------------
__device__ float g_wq[(size_t)NN * TWO_D];                  // wq = [v|t] @ W.T
__device__ __nv_bfloat16 g_A2[(size_t)MP * KP];             // [Ahi | Alo | Ahi]
__device__ __nv_bfloat16 g_B2[(size_t)TWO_D * KP];          // [Whi | Whi | Wlo]

// ---------------------------------------------------------------------------
// helpers
// ---------------------------------------------------------------------------
__device__ __forceinline__ uint32_t smem_u32(const void* p) {
    uint32_t a;
    asm("{ .reg .u64 t; cvta.to.shared.u64 t, %1; cvt.u32.u64 %0, t; }" : "=r"(a) : "l"(p));
    return a;
}
__device__ __forceinline__ void ldsm_x4(uint32_t* r, uint32_t addr) {
    asm volatile("ldmatrix.sync.aligned.m8n8.x4.shared.b16 {%0,%1,%2,%3}, [%4];"
                 : "=r"(r[0]), "=r"(r[1]), "=r"(r[2]), "=r"(r[3]) : "r"(addr));
}
__device__ __forceinline__ void mma16816(float* d, const uint32_t* a, uint32_t b0, uint32_t b1) {
    asm volatile(
        "mma.sync.aligned.m16n8k16.row.col.f32.bf16.bf16.f32 "
        "{%0,%1,%2,%3}, {%4,%5,%6,%7}, {%8,%9}, {%0,%1,%2,%3};"
        : "+f"(d[0]), "+f"(d[1]), "+f"(d[2]), "+f"(d[3])
        : "r"(a[0]), "r"(a[1]), "r"(a[2]), "r"(a[3]), "r"(b0), "r"(b1));
}
__device__ __forceinline__ void cp16(uint32_t saddr, const void* gaddr) {
    asm volatile("cp.async.cg.shared.global [%0], [%1], 16;" :: "r"(saddr), "l"(gaddr));
}
__device__ __forceinline__ void cp_commit() {
    asm volatile("cp.async.commit_group;" ::: "memory");
}

// ---------------------------------------------------------------------------
// Kernel 0: fp32 -> bf16 hi/lo split, written as concatenated-K layout.
// A2[n] = [hi(v|t)(256) | lo(v|t)(256) | hi(v|t)(256)]
// B2[j] = [hi(W_j)(256) | hi(W_j)(256) | lo(W_j)(256)]
// ---------------------------------------------------------------------------
__global__ __launch_bounds__(256) void convert_split(const float* __restrict__ v_fea,
                                                     const float* __restrict__ t_emb,
                                                     const float* __restrict__ W) {
    const int totalA = MP * 64;          // ushort4 quads per 256-col row
    const int totalW = TWO_D * 64;
    int i = blockIdx.x * blockDim.x + threadIdx.x;
    if (i < totalA) {
        int n = i >> 6;
        int c = (i & 63) * 4;
        ushort4 hv = make_ushort4(0, 0, 0, 0), lv = make_ushort4(0, 0, 0, 0);
        if (n < NN) {
            const float* src = (c < DD) ? (v_fea + (size_t)n * DD + c)
                                        : (t_emb + (size_t)n * DD + (c - DD));
            float4 x = *(const float4*)src;
            __nv_bfloat16 hx = __float2bfloat16_rn(x.x);
            __nv_bfloat16 hy = __float2bfloat16_rn(x.y);
            __nv_bfloat16 hz = __float2bfloat16_rn(x.z);
            __nv_bfloat16 hw = __float2bfloat16_rn(x.w);
            hv = make_ushort4(__bfloat16_as_ushort(hx), __bfloat16_as_ushort(hy),
                              __bfloat16_as_ushort(hz), __bfloat16_as_ushort(hw));
            lv = make_ushort4(
                __bfloat16_as_ushort(__float2bfloat16_rn(x.x - __bfloat162float(hx))),
                __bfloat16_as_ushort(__float2bfloat16_rn(x.y - __bfloat162float(hy))),
                __bfloat16_as_ushort(__float2bfloat16_rn(x.z - __bfloat162float(hz))),
                __bfloat16_as_ushort(__float2bfloat16_rn(x.w - __bfloat162float(hw))));
        }
        ushort4* row = (ushort4*)(g_A2 + (size_t)n * KP);
        row[(c >> 2)] = hv;                 // hi at [0,256)
        row[(c >> 2) + 64] = lv;            // lo at [256,512)
        row[(c >> 2) + 128] = hv;           // hi at [512,768)
    } else if (i < totalA + totalW) {
        int t = i - totalA;
        int j = t >> 6;
        int c = (t & 63) * 4;
        float4 x = *(const float4*)(W + (size_t)j * TWO_D + c);
        __nv_bfloat16 hx = __float2bfloat16_rn(x.x);
        __nv_bfloat16 hy = __float2bfloat16_rn(x.y);
        __nv_bfloat16 hz = __float2bfloat16_rn(x.z);
        __nv_bfloat16 hw = __float2bfloat16_rn(x.w);
        ushort4 hv = make_ushort4(__bfloat16_as_ushort(hx), __bfloat16_as_ushort(hy),
                                  __bfloat16_as_ushort(hz), __bfloat16_as_ushort(hw));
        ushort4 lv = make_ushort4(
            __bfloat16_as_ushort(__float2bfloat16_rn(x.x - __bfloat162float(hx))),
            __bfloat16_as_ushort(__float2bfloat16_rn(x.y - __bfloat162float(hy))),
            __bfloat16_as_ushort(__float2bfloat16_rn(x.z - __bfloat162float(hz))),
            __bfloat16_as_ushort(__float2bfloat16_rn(x.w - __bfloat162float(hw))));
        ushort4* row = (ushort4*)(g_B2 + (size_t)j * KP);
        row[(c >> 2)] = hv;                 // hi
        row[(c >> 2) + 64] = hv;            // hi
        row[(c >> 2) + 128] = lv;           // lo
    }
}

// ---------------------------------------------------------------------------
// Kernel 1: bf16 mma.sync GEMM  g_wq[m][n] = sum_k A2[m][k] * B2[n][k]
// BM=128 BN=128 BK=32, 256 thr (8 warps, 4m x 2n; warp tile 32x64),
// cp.async 3-stage pipeline, 80B-padded smem rows, ldmatrix.x4 fragments.
// ---------------------------------------------------------------------------
#define ROWB 80                       // bytes per padded 32-elem bf16 row
#define STAGE_A (128 * ROWB)          // 10240
#define STAGE_BYTES (2 * 128 * ROWB)  // A + B = 20480
#define NSTAGE 3
#define GEMM_SMEM (NSTAGE * STAGE_BYTES)
#define NCHUNK (KP / 32)              // 24

__global__ __launch_bounds__(256) void wq_gemm_mma() {
    extern __shared__ char smem[];
    const uint32_t sbase = smem_u32(smem);
    const int tid = threadIdx.x;
    const int lane = tid & 31, w = tid >> 5;
    const int wm = w >> 1, wn = w & 1;
    const int m0 = blockIdx.x * 128;
    const int n0 = blockIdx.y * 128;

    float acc[2][8][4];
#pragma unroll
    for (int i = 0; i < 2; i++)
#pragma unroll
        for (int j = 0; j < 8; j++)
#pragma unroll
            for (int q = 0; q < 4; q++) acc[i][j][q] = 0.f;

    // per-thread load slots: 2 for A + 2 for B
    const int arow0 = tid >> 2, aseg = tid & 3;   // rows 0..63 / segs
    // prologue: stages 0..2 <- chunks 0..2
#pragma unroll
    for (int c = 0; c < NSTAGE; c++) {
        uint32_t st = sbase + c * STAGE_BYTES;
#pragma unroll
        for (int it = 0; it < 2; it++) {
            int row = arow0 + it * 64;
            cp16(st + row * ROWB + aseg * 16,
                 g_A2 + (size_t)(m0 + row) * KP + c * 32 + aseg * 8);
            cp16(st + STAGE_A + row * ROWB + aseg * 16,
                 g_B2 + (size_t)(n0 + row) * KP + c * 32 + aseg * 8);
        }
        cp_commit();
    }

    for (int c = 0; c < NCHUNK; c++) {
        if (c >= NCHUNK - 2) {
            asm volatile("cp.async.wait_group 0;" ::: "memory");
        } else {
            asm volatile("cp.async.wait_group 2;" ::: "memory");
        }
        __syncthreads();

        const uint32_t st = sbase + (c % NSTAGE) * STAGE_BYTES;
        const uint32_t aB = st, bB = st + STAGE_A;

#pragma unroll
        for (int ks = 0; ks < 2; ks++) {
            uint32_t afr[2][4], bfr[4][4];
#pragma unroll
            for (int mi = 0; mi < 2; mi++) {
                int row = wm * 32 + mi * 16 + (lane & 15);
                ldsm_x4(afr[mi], aB + row * ROWB + ks * 32 + ((lane >> 4) << 4));
            }
#pragma unroll
            for (int nj2 = 0; nj2 < 4; nj2++) {
                int row = wn * 64 + nj2 * 16 + (lane & 15);
                ldsm_x4(bfr[nj2], bB + row * ROWB + ks * 32 + ((lane >> 4) << 4));
            }
#pragma unroll
            for (int mi = 0; mi < 2; mi++)
#pragma unroll
                for (int nj = 0; nj < 8; nj++) {
                    uint32_t b0 = bfr[nj >> 1][nj & 1];
                    uint32_t b1 = bfr[nj >> 1][2 + (nj & 1)];
                    mma16816(acc[mi][nj], afr[mi], b0, b1);
                }
        }
        __syncthreads();

        int cn = c + NSTAGE;
        if (cn < NCHUNK) {
            uint32_t stn = sbase + (cn % NSTAGE) * STAGE_BYTES;
#pragma unroll
            for (int it = 0; it < 2; it++) {
                int row = arow0 + it * 64;
                cp16(stn + row * ROWB + aseg * 16,
                     g_A2 + (size_t)(m0 + row) * KP + cn * 32 + aseg * 8);
                cp16(stn + STAGE_A + row * ROWB + aseg * 16,
                     g_B2 + (size_t)(n0 + row) * KP + cn * 32 + aseg * 8);
            }
        }
        cp_commit();   // commit every iter to keep group accounting uniform
    }

    // epilogue
    const int gid = lane >> 2, tig = lane & 3;
#pragma unroll
    for (int mi = 0; mi < 2; mi++) {
        int mrow = m0 + wm * 32 + mi * 16 + gid;
#pragma unroll
        for (int nj = 0; nj < 8; nj++) {
            int col = n0 + wn * 64 + nj * 8 + tig * 2;
            if (mrow < NN)
                *(float2*)(g_wq + (size_t)mrow * TWO_D + col) =
                    make_float2(acc[mi][nj][0], acc[mi][nj][1]);
            if (mrow + 8 < NN)
                *(float2*)(g_wq + (size_t)(mrow + 8) * TWO_D + col) =
                    make_float2(acc[mi][nj][2], acc[mi][nj][3]);
        }
    }
}

// ---------------------------------------------------------------------------
// Kernel 2: per-node edge attention with online softmax (unchanged).
// ---------------------------------------------------------------------------
__global__ __launch_bounds__(256) void edge_attn(const float* __restrict__ v_fea,
                                                 const float* __restrict__ t_emb,
                                                 const int* __restrict__ ef,
                                                 float* __restrict__ out) {
    const int warp = (blockIdx.x * blockDim.x + threadIdx.x) >> 5;
    const int lane = threadIdx.x & 31;
    if (warp >= NN) return;

    const float* wqr = g_wq + (size_t)warp * TWO_D;
    const float4 wqa = *(const float4*)(wqr + lane * 4);
    const float4 wqb = *(const float4*)(wqr + DD + lane * 4);

    const int e_mine = ef[(size_t)warp * KK + lane];

    float m = -INFINITY;
    float s = 0.f;
    float4 acc = make_float4(0.f, 0.f, 0.f, 0.f);

#pragma unroll 4
    for (int k = 0; k < KK; k++) {
        int e = __shfl_sync(0xffffffffu, e_mine, k);
        const float4 v = *(const float4*)(v_fea + (size_t)e * DD + lane * 4);
        const float4 t = *(const float4*)(t_emb + (size_t)e * DD + lane * 4);

        float p = v.x * wqa.x + v.y * wqa.y + v.z * wqa.z + v.w * wqa.w
                + t.x * wqb.x + t.y * wqb.y + t.z * wqb.z + t.w * wqb.w;
        p += __shfl_xor_sync(0xffffffffu, p, 16);
        p += __shfl_xor_sync(0xffffffffu, p, 8);
        p += __shfl_xor_sync(0xffffffffu, p, 4);
        p += __shfl_xor_sync(0xffffffffu, p, 2);
        p += __shfl_xor_sync(0xffffffffu, p, 1);

        float mn = fmaxf(m, p);
        float c = __expf(m - mn);
        float wgt = __expf(p - mn);
        s = s * c + wgt;
        acc.x = acc.x * c + wgt * v.x;
        acc.y = acc.y * c + wgt * v.y;
        acc.z = acc.z * c + wgt * v.z;
        acc.w = acc.w * c + wgt * v.w;
        m = mn;
    }

    const float inv = 1.f / s;
    float4 o = make_float4(acc.x * inv, acc.y * inv, acc.z * inv, acc.w * inv);
    *(float4*)(out + (size_t)warp * DD + lane * 4) = o;
}

// ---------------------------------------------------------------------------
extern "C" void kernel_launch(void* const* d_in, const int* in_sizes, int n_in,
                              void* d_out, int out_size) {
    const float* v_fea = (const float*)d_in[0];
    const float* t_emb = (const float*)d_in[1];
    const int* ef = (const int*)d_in[2];
    const float* W = (const float*)d_in[3];
    float* out = (float*)d_out;

    cudaFuncSetAttribute(wq_gemm_mma, cudaFuncAttributeMaxDynamicSharedMemorySize, GEMM_SMEM);

    const int totalConv = MP * 64 + TWO_D * 64;
    convert_split<<<(totalConv + 255) / 256, 256>>>(v_fea, t_emb, W);

    wq_gemm_mma<<<dim3(MP / 128, TWO_D / 128), 256, GEMM_SMEM>>>();

    int grid2 = (NN + 7) / 8;
    edge_attn<<<grid2, 256>>>(v_fea, t_emb, ef, out);
}

// round 5
// speedup vs baseline: 1.3450x; 1.0513x over previous
#include <cuda_runtime.h>
#include <cuda_bf16.h>
#include <math.h>
#include <stdint.h>

#define NN 50000
#define MP 50048          // NN padded to 128
#define DD 128
#define KK 32
#define TWO_D 256
#define KP 512            // [hi(256) | lo(256)]

// ---------------------------------------------------------------------------
// Global scratch
// ---------------------------------------------------------------------------
__device__ float g_wq[(size_t)NN * TWO_D];                  // wq = [v|t] @ W.T
__device__ __nv_bfloat16 g_A2[(size_t)MP * KP];             // [Ahi | Alo]
__device__ __nv_bfloat16 g_B2[(size_t)TWO_D * KP];          // [Whi | Wlo]

// ---------------------------------------------------------------------------
// helpers
// ---------------------------------------------------------------------------
__device__ __forceinline__ uint32_t smem_u32(const void* p) {
    uint32_t a;
    asm("{ .reg .u64 t; cvta.to.shared.u64 t, %1; cvt.u32.u64 %0, t; }" : "=r"(a) : "l"(p));
    return a;
}
__device__ __forceinline__ void ldsm_x4(uint32_t* r, uint32_t addr) {
    asm volatile("ldmatrix.sync.aligned.m8n8.x4.shared.b16 {%0,%1,%2,%3}, [%4];"
                 : "=r"(r[0]), "=r"(r[1]), "=r"(r[2]), "=r"(r[3]) : "r"(addr));
}
__device__ __forceinline__ void mma16816(float* d, const uint32_t* a, uint32_t b0, uint32_t b1) {
    asm volatile(
        "mma.sync.aligned.m16n8k16.row.col.f32.bf16.bf16.f32 "
        "{%0,%1,%2,%3}, {%4,%5,%6,%7}, {%8,%9}, {%0,%1,%2,%3};"
        : "+f"(d[0]), "+f"(d[1]), "+f"(d[2]), "+f"(d[3])
        : "r"(a[0]), "r"(a[1]), "r"(a[2]), "r"(a[3]), "r"(b0), "r"(b1));
}
__device__ __forceinline__ void cp16(uint32_t saddr, const void* gaddr) {
    asm volatile("cp.async.cg.shared.global [%0], [%1], 16;" :: "r"(saddr), "l"(gaddr));
}
__device__ __forceinline__ void cp_commit() {
    asm volatile("cp.async.commit_group;" ::: "memory");
}

// ---------------------------------------------------------------------------
// Kernel 0: fp32 -> bf16 hi/lo split.
// A2[n] = [hi(v|t)(256) | lo(v|t)(256)],  B2[j] = [hi(W_j) | lo(W_j)]
// ---------------------------------------------------------------------------
__global__ __launch_bounds__(256) void convert_split(const float* __restrict__ v_fea,
                                                     const float* __restrict__ t_emb,
                                                     const float* __restrict__ W) {
    const int totalA = MP * 64;          // ushort4 quads per 256-col row
    const int totalW = TWO_D * 64;
    int i = blockIdx.x * blockDim.x + threadIdx.x;
    if (i < totalA) {
        int n = i >> 6;
        int c = (i & 63) * 4;
        ushort4 hv = make_ushort4(0, 0, 0, 0), lv = make_ushort4(0, 0, 0, 0);
        if (n < NN) {
            const float* src = (c < DD) ? (v_fea + (size_t)n * DD + c)
                                        : (t_emb + (size_t)n * DD + (c - DD));
            float4 x = *(const float4*)src;
            __nv_bfloat16 hx = __float2bfloat16_rn(x.x);
            __nv_bfloat16 hy = __float2bfloat16_rn(x.y);
            __nv_bfloat16 hz = __float2bfloat16_rn(x.z);
            __nv_bfloat16 hw = __float2bfloat16_rn(x.w);
            hv = make_ushort4(__bfloat16_as_ushort(hx), __bfloat16_as_ushort(hy),
                              __bfloat16_as_ushort(hz), __bfloat16_as_ushort(hw));
            lv = make_ushort4(
                __bfloat16_as_ushort(__float2bfloat16_rn(x.x - __bfloat162float(hx))),
                __bfloat16_as_ushort(__float2bfloat16_rn(x.y - __bfloat162float(hy))),
                __bfloat16_as_ushort(__float2bfloat16_rn(x.z - __bfloat162float(hz))),
                __bfloat16_as_ushort(__float2bfloat16_rn(x.w - __bfloat162float(hw))));
        }
        ushort4* row = (ushort4*)(g_A2 + (size_t)n * KP);
        row[(c >> 2)] = hv;                 // hi at [0,256)
        row[(c >> 2) + 64] = lv;            // lo at [256,512)
    } else if (i < totalA + totalW) {
        int t = i - totalA;
        int j = t >> 6;
        int c = (t & 63) * 4;
        float4 x = *(const float4*)(W + (size_t)j * TWO_D + c);
        __nv_bfloat16 hx = __float2bfloat16_rn(x.x);
        __nv_bfloat16 hy = __float2bfloat16_rn(x.y);
        __nv_bfloat16 hz = __float2bfloat16_rn(x.z);
        __nv_bfloat16 hw = __float2bfloat16_rn(x.w);
        ushort4 hv = make_ushort4(__bfloat16_as_ushort(hx), __bfloat16_as_ushort(hy),
                                  __bfloat16_as_ushort(hz), __bfloat16_as_ushort(hw));
        ushort4 lv = make_ushort4(
            __bfloat16_as_ushort(__float2bfloat16_rn(x.x - __bfloat162float(hx))),
            __bfloat16_as_ushort(__float2bfloat16_rn(x.y - __bfloat162float(hy))),
            __bfloat16_as_ushort(__float2bfloat16_rn(x.z - __bfloat162float(hz))),
            __bfloat16_as_ushort(__float2bfloat16_rn(x.w - __bfloat162float(hw))));
        ushort4* row = (ushort4*)(g_B2 + (size_t)j * KP);
        row[(c >> 2)] = hv;
        row[(c >> 2) + 64] = lv;
    }
}

// ---------------------------------------------------------------------------
// Kernel 1: bf16 mma.sync GEMM over 24 virtual K-chunks (3 passes x 8):
//   pass0: Ahi*Whi   pass1: Alo*Whi   pass2: Ahi*Wlo
// BM=128 BN=128, 256 thr (8 warps 4x2, warp tile 32x64),
// cp.async 4-stage single-sync multistage pipeline, 80B-padded smem rows.
// ---------------------------------------------------------------------------
#define ROWB 80                       // bytes per padded 32-elem bf16 row
#define STAGE_A (128 * ROWB)          // 10240
#define STAGE_BYTES (2 * 128 * ROWB)  // A + B = 20480
#define NSTAGE 4
#define GEMM_SMEM (NSTAGE * STAGE_BYTES)
#define NCHUNK 24

// chunk -> (A col, B col) in elements within KP=512 row
__device__ __forceinline__ int chunk_acol(int c) {
    int p = c >> 3, k = c & 7;
    return (p == 1 ? (8 + k) : k) * 32;
}
__device__ __forceinline__ int chunk_bcol(int c) {
    int p = c >> 3, k = c & 7;
    return (p == 2 ? (8 + k) : k) * 32;
}

__global__ __launch_bounds__(256) void wq_gemm_mma() {
    extern __shared__ char smem[];
    const uint32_t sbase = smem_u32(smem);
    const int tid = threadIdx.x;
    const int lane = tid & 31, w = tid >> 5;
    const int wm = w >> 1, wn = w & 1;
    const int m0 = blockIdx.x * 128;
    const int n0 = blockIdx.y * 128;

    float acc[2][8][4];
#pragma unroll
    for (int i = 0; i < 2; i++)
#pragma unroll
        for (int j = 0; j < 8; j++)
#pragma unroll
            for (int q = 0; q < 4; q++) acc[i][j][q] = 0.f;

    const int arow0 = tid >> 2, aseg = tid & 3;

    // prologue: chunks 0..2 -> stages 0..2
#pragma unroll
    for (int c = 0; c < NSTAGE - 1; c++) {
        uint32_t st = sbase + c * STAGE_BYTES;
        int ac = chunk_acol(c), bc = chunk_bcol(c);
#pragma unroll
        for (int it = 0; it < 2; it++) {
            int row = arow0 + it * 64;
            cp16(st + row * ROWB + aseg * 16,
                 g_A2 + (size_t)(m0 + row) * KP + ac + aseg * 8);
            cp16(st + STAGE_A + row * ROWB + aseg * 16,
                 g_B2 + (size_t)(n0 + row) * KP + bc + aseg * 8);
        }
        cp_commit();
    }

    for (int c = 0; c < NCHUNK; c++) {
        asm volatile("cp.async.wait_group %0;" :: "n"(NSTAGE - 2) : "memory");
        __syncthreads();

        // prefetch chunk c+3 into stage (c+3)%4 == (c-1)%4 (drained last iter)
        int cn = c + NSTAGE - 1;
        if (cn < NCHUNK) {
            uint32_t stn = sbase + (cn % NSTAGE) * STAGE_BYTES;
            int ac = chunk_acol(cn), bc = chunk_bcol(cn);
#pragma unroll
            for (int it = 0; it < 2; it++) {
                int row = arow0 + it * 64;
                cp16(stn + row * ROWB + aseg * 16,
                     g_A2 + (size_t)(m0 + row) * KP + ac + aseg * 8);
                cp16(stn + STAGE_A + row * ROWB + aseg * 16,
                     g_B2 + (size_t)(n0 + row) * KP + bc + aseg * 8);
            }
        }
        cp_commit();   // uniform group accounting (empty group in tail)

        const uint32_t st = sbase + (c % NSTAGE) * STAGE_BYTES;
        const uint32_t aB = st, bB = st + STAGE_A;

#pragma unroll
        for (int ks = 0; ks < 2; ks++) {
            uint32_t afr[2][4], bfr[4][4];
#pragma unroll
            for (int mi = 0; mi < 2; mi++) {
                int row = wm * 32 + mi * 16 + (lane & 15);
                ldsm_x4(afr[mi], aB + row * ROWB + ks * 32 + ((lane >> 4) << 4));
            }
#pragma unroll
            for (int nj2 = 0; nj2 < 4; nj2++) {
                int row = wn * 64 + nj2 * 16 + (lane & 15);
                ldsm_x4(bfr[nj2], bB + row * ROWB + ks * 32 + ((lane >> 4) << 4));
            }
#pragma unroll
            for (int mi = 0; mi < 2; mi++)
#pragma unroll
                for (int nj = 0; nj < 8; nj++) {
                    uint32_t b0 = bfr[nj >> 1][nj & 1];
                    uint32_t b1 = bfr[nj >> 1][2 + (nj & 1)];
                    mma16816(acc[mi][nj], afr[mi], b0, b1);
                }
        }
    }

    // epilogue
    const int gid = lane >> 2, tig = lane & 3;
#pragma unroll
    for (int mi = 0; mi < 2; mi++) {
        int mrow = m0 + wm * 32 + mi * 16 + gid;
#pragma unroll
        for (int nj = 0; nj < 8; nj++) {
            int col = n0 + wn * 64 + nj * 8 + tig * 2;
            if (mrow < NN)
                *(float2*)(g_wq + (size_t)mrow * TWO_D + col) =
                    make_float2(acc[mi][nj][0], acc[mi][nj][1]);
            if (mrow + 8 < NN)
                *(float2*)(g_wq + (size_t)(mrow + 8) * TWO_D + col) =
                    make_float2(acc[mi][nj][2], acc[mi][nj][3]);
        }
    }
}

// ---------------------------------------------------------------------------
// Kernel 2: per-node edge attention, TWO independent online-softmax chains
// (even/odd neighbors) merged at the end -> halved serial dependency depth.
// ---------------------------------------------------------------------------
__global__ __launch_bounds__(256) void edge_attn(const float* __restrict__ v_fea,
                                                 const float* __restrict__ t_emb,
                                                 const int* __restrict__ ef,
                                                 float* __restrict__ out) {
    const int warp = (blockIdx.x * blockDim.x + threadIdx.x) >> 5;
    const int lane = threadIdx.x & 31;
    if (warp >= NN) return;

    const float* wqr = g_wq + (size_t)warp * TWO_D;
    const float4 wqa = *(const float4*)(wqr + lane * 4);
    const float4 wqb = *(const float4*)(wqr + DD + lane * 4);

    const int e_mine = ef[(size_t)warp * KK + lane];

    float m1 = -INFINITY, s1 = 0.f;
    float m2 = -INFINITY, s2 = 0.f;
    float4 a1 = make_float4(0.f, 0.f, 0.f, 0.f);
    float4 a2 = make_float4(0.f, 0.f, 0.f, 0.f);

#pragma unroll 2
    for (int k = 0; k < KK; k += 2) {
        int e1 = __shfl_sync(0xffffffffu, e_mine, k);
        int e2 = __shfl_sync(0xffffffffu, e_mine, k + 1);
        const float4 v1 = *(const float4*)(v_fea + (size_t)e1 * DD + lane * 4);
        const float4 t1 = *(const float4*)(t_emb + (size_t)e1 * DD + lane * 4);
        const float4 v2 = *(const float4*)(v_fea + (size_t)e2 * DD + lane * 4);
        const float4 t2 = *(const float4*)(t_emb + (size_t)e2 * DD + lane * 4);

        float p1 = v1.x * wqa.x + v1.y * wqa.y + v1.z * wqa.z + v1.w * wqa.w
                 + t1.x * wqb.x + t1.y * wqb.y + t1.z * wqb.z + t1.w * wqb.w;
        float p2 = v2.x * wqa.x + v2.y * wqa.y + v2.z * wqa.z + v2.w * wqa.w
                 + t2.x * wqb.x + t2.y * wqb.y + t2.z * wqb.z + t2.w * wqb.w;
        // interleaved butterfly reduces (two independent chains)
        p1 += __shfl_xor_sync(0xffffffffu, p1, 16);
        p2 += __shfl_xor_sync(0xffffffffu, p2, 16);
        p1 += __shfl_xor_sync(0xffffffffu, p1, 8);
        p2 += __shfl_xor_sync(0xffffffffu, p2, 8);
        p1 += __shfl_xor_sync(0xffffffffu, p1, 4);
        p2 += __shfl_xor_sync(0xffffffffu, p2, 4);
        p1 += __shfl_xor_sync(0xffffffffu, p1, 2);
        p2 += __shfl_xor_sync(0xffffffffu, p2, 2);
        p1 += __shfl_xor_sync(0xffffffffu, p1, 1);
        p2 += __shfl_xor_sync(0xffffffffu, p2, 1);

        float mn1 = fmaxf(m1, p1);
        float c1 = __expf(m1 - mn1);
        float w1 = __expf(p1 - mn1);
        s1 = s1 * c1 + w1;
        a1.x = a1.x * c1 + w1 * v1.x;
        a1.y = a1.y * c1 + w1 * v1.y;
        a1.z = a1.z * c1 + w1 * v1.z;
        a1.w = a1.w * c1 + w1 * v1.w;
        m1 = mn1;

        float mn2 = fmaxf(m2, p2);
        float c2 = __expf(m2 - mn2);
        float w2 = __expf(p2 - mn2);
        s2 = s2 * c2 + w2;
        a2.x = a2.x * c2 + w2 * v2.x;
        a2.y = a2.y * c2 + w2 * v2.y;
        a2.z = a2.z * c2 + w2 * v2.z;
        a2.w = a2.w * c2 + w2 * v2.w;
        m2 = mn2;
    }

    // merge the two chains
    float mn = fmaxf(m1, m2);
    float c1 = __expf(m1 - mn), c2 = __expf(m2 - mn);
    float s = s1 * c1 + s2 * c2;
    const float inv = 1.f / s;
    float4 o;
    o.x = (a1.x * c1 + a2.x * c2) * inv;
    o.y = (a1.y * c1 + a2.y * c2) * inv;
    o.z = (a1.z * c1 + a2.z * c2) * inv;
    o.w = (a1.w * c1 + a2.w * c2) * inv;
    *(float4*)(out + (size_t)warp * DD + lane * 4) = o;
}

// ---------------------------------------------------------------------------
extern "C" void kernel_launch(void* const* d_in, const int* in_sizes, int n_in,
                              void* d_out, int out_size) {
    const float* v_fea = (const float*)d_in[0];
    const float* t_emb = (const float*)d_in[1];
    const int* ef = (const int*)d_in[2];
    const float* W = (const float*)d_in[3];
    float* out = (float*)d_out;

    cudaFuncSetAttribute(wq_gemm_mma, cudaFuncAttributeMaxDynamicSharedMemorySize, GEMM_SMEM);

    const int totalConv = MP * 64 + TWO_D * 64;
    convert_split<<<(totalConv + 255) / 256, 256>>>(v_fea, t_emb, W);

    wq_gemm_mma<<<dim3(MP / 128, TWO_D / 128), 256, GEMM_SMEM>>>();

    int grid2 = (NN + 7) / 8;
    edge_attn<<<grid2, 256>>>(v_fea, t_emb, ef, out);
}

// round 6
// speedup vs baseline: 1.3725x; 1.0205x over previous
#include <cuda_runtime.h>
#include <cuda_bf16.h>
#include <math.h>
#include <stdint.h>

#define NN 50000
#define MP 50048          // NN padded to 128
#define DD 128
#define KK 32
#define TWO_D 256

// ---------------------------------------------------------------------------
// Global scratch
// ---------------------------------------------------------------------------
__device__ float g_wq[(size_t)NN * TWO_D];                  // wq = [v|t] @ W.T

// ---------------------------------------------------------------------------
// helpers
// ---------------------------------------------------------------------------
__device__ __forceinline__ uint32_t smem_u32(const void* p) {
    uint32_t a;
    asm("{ .reg .u64 t; cvta.to.shared.u64 t, %1; cvt.u32.u64 %0, t; }" : "=r"(a) : "l"(p));
    return a;
}
__device__ __forceinline__ void ldsm_x4(uint32_t* r, uint32_t addr) {
    asm volatile("ldmatrix.sync.aligned.m8n8.x4.shared.b16 {%0,%1,%2,%3}, [%4];"
                 : "=r"(r[0]), "=r"(r[1]), "=r"(r[2]), "=r"(r[3]) : "r"(addr));
}
__device__ __forceinline__ void mma16816(float* d, const uint32_t* a, uint32_t b0, uint32_t b1) {
    asm volatile(
        "mma.sync.aligned.m16n8k16.row.col.f32.bf16.bf16.f32 "
        "{%0,%1,%2,%3}, {%4,%5,%6,%7}, {%8,%9}, {%0,%1,%2,%3};"
        : "+f"(d[0]), "+f"(d[1]), "+f"(d[2]), "+f"(d[3])
        : "r"(a[0]), "r"(a[1]), "r"(a[2]), "r"(a[3]), "r"(b0), "r"(b1));
}
// cp.async with src-size (0 => zero-fill destination)
__device__ __forceinline__ void cp16z(uint32_t saddr, const void* gaddr, uint32_t sz) {
    asm volatile("cp.async.cg.shared.global [%0], [%1], 16, %2;"
                 :: "r"(saddr), "l"(gaddr), "r"(sz));
}
__device__ __forceinline__ void cp_commit() {
    asm volatile("cp.async.commit_group;" ::: "memory");
}

// ---------------------------------------------------------------------------
// Fused GEMM: g_wq[m][j] = sum_k A[m][k] * W[j][k], A = [v_fea | t_emb] fp32.
// Per CTA: BM=128, BN=128. 8 k-chunks of 32. Per chunk: cp.async fp32 chunks,
// in-kernel bf16 hi/lo split, 3 accumulating HMMA products:
//   Ahi*Whi + Alo*Whi + Ahi*Wlo  (lo*lo dropped, ~2^-16 rel)
// ---------------------------------------------------------------------------
#define ROWF 144                      // fp32 staging: 32 floats (128B) + 16B pad
#define STG_SZ (128 * ROWF)           // 18432 per matrix per slot
#define ROWB 80                       // bf16 row: 32 bf16 (64B) + 16B pad
#define BUF_SZ (128 * ROWB)           // 10240
// smem: stgA[2] @ 0, 18432; stgB[2] @ 36864, 55296;
//       bf16 stage s: 73728 + s*40960 + {Ahi:0, Alo:10240, Bhi:20480, Blo:30720}
#define STGB_OFF 36864
#define BF_BASE 73728
#define GEMM_SMEM (BF_BASE + 2 * 4 * BUF_SZ)   // 155648

__device__ __forceinline__ void load_chunk(uint32_t sbase, int c, int m0, int n0,
                                           const float* __restrict__ v_fea,
                                           const float* __restrict__ t_emb,
                                           const float* __restrict__ W, int tid) {
    const uint32_t stgA = sbase + (c & 1) * STG_SZ;
    const uint32_t stgB = sbase + STGB_OFF + (c & 1) * STG_SZ;
    const float* asrc = (c < 4) ? v_fea : t_emb;
    const int col0 = (c & 3) * 32;
#pragma unroll
    for (int g = 0; g < 4; g++) {
        int idx = g * 256 + tid;          // 0..1023, coalesced
        int row = idx >> 3, seg = idx & 7;
        uint32_t szA = (m0 + row < NN) ? 16u : 0u;
        cp16z(stgA + row * ROWF + seg * 16,
              asrc + (size_t)(m0 + row) * DD + col0 + seg * 4, szA);
        cp16z(stgB + row * ROWF + seg * 16,
              W + (size_t)(n0 + row) * TWO_D + c * 32 + seg * 4, 16u);
    }
    cp_commit();
}

__device__ __forceinline__ void convert_chunk(char* smemc, int c, int tid) {
    const int s = c & 1;
    const int row = tid >> 1;
    const int c0 = (tid & 1) * 16;
#pragma unroll
    for (int mat = 0; mat < 2; mat++) {
        const char* stg = smemc + mat * STGB_OFF + s * STG_SZ;
        char* bhi = smemc + BF_BASE + s * 40960 + mat * 20480;
        char* blo = bhi + BUF_SZ;
#pragma unroll
        for (int i = 0; i < 4; i++) {
            const int cc = c0 + i * 4;
            float4 x = *(const float4*)(stg + row * ROWF + cc * 4);
            __nv_bfloat162 h01 = __floats2bfloat162_rn(x.x, x.y);
            __nv_bfloat162 h23 = __floats2bfloat162_rn(x.z, x.w);
            float l0 = x.x - __bfloat162float(h01.x);
            float l1 = x.y - __bfloat162float(h01.y);
            float l2 = x.z - __bfloat162float(h23.x);
            float l3 = x.w - __bfloat162float(h23.y);
            __nv_bfloat162 lo01 = __floats2bfloat162_rn(l0, l1);
            __nv_bfloat162 lo23 = __floats2bfloat162_rn(l2, l3);
            uint2 hv = make_uint2(*(uint32_t*)&h01, *(uint32_t*)&h23);
            uint2 lv = make_uint2(*(uint32_t*)&lo01, *(uint32_t*)&lo23);
            *(uint2*)(bhi + row * ROWB + cc * 2) = hv;
            *(uint2*)(blo + row * ROWB + cc * 2) = lv;
        }
    }
}

__global__ __launch_bounds__(256) void wq_gemm_fused(const float* __restrict__ v_fea,
                                                     const float* __restrict__ t_emb,
                                                     const float* __restrict__ W) {
    extern __shared__ char smem[];
    const uint32_t sbase = smem_u32(smem);
    const int tid = threadIdx.x;
    const int lane = tid & 31, w = tid >> 5;
    const int wm = w >> 1, wn = w & 1;
    const int m0 = blockIdx.x * 128;
    const int n0 = blockIdx.y * 128;

    float acc[2][8][4];
#pragma unroll
    for (int i = 0; i < 2; i++)
#pragma unroll
        for (int j = 0; j < 8; j++)
#pragma unroll
            for (int q = 0; q < 4; q++) acc[i][j][q] = 0.f;

    // prologue: stage chunks 0,1; convert chunk 0
    load_chunk(sbase, 0, m0, n0, v_fea, t_emb, W, tid);
    load_chunk(sbase, 1, m0, n0, v_fea, t_emb, W, tid);
    asm volatile("cp.async.wait_group 1;" ::: "memory");
    __syncthreads();
    convert_chunk(smem, 0, tid);
    __syncthreads();

    for (int c = 0; c < 8; c++) {
        if (c + 1 < 8) {
            asm volatile("cp.async.wait_group 0;" ::: "memory");
            __syncthreads();
            convert_chunk(smem, c + 1, tid);
            if (c + 2 < 8)
                load_chunk(sbase, c + 2, m0, n0, v_fea, t_emb, W, tid);
        }

        // MMA on bf16 stage c&1 (written by convert in previous iter, sync'd)
        const uint32_t aH = sbase + BF_BASE + (c & 1) * 40960;
        const uint32_t aL = aH + BUF_SZ;
        const uint32_t bH = aH + 2 * BUF_SZ;
        const uint32_t bL = aH + 3 * BUF_SZ;

#pragma unroll
        for (int ks = 0; ks < 2; ks++) {
            uint32_t afh[2][4], afl[2][4], bfh[4][4], bfl[4][4];
#pragma unroll
            for (int mi = 0; mi < 2; mi++) {
                int row = wm * 32 + mi * 16 + (lane & 15);
                uint32_t o = row * ROWB + ks * 32 + ((lane >> 4) << 4);
                ldsm_x4(afh[mi], aH + o);
                ldsm_x4(afl[mi], aL + o);
            }
#pragma unroll
            for (int nj = 0; nj < 4; nj++) {
                int row = wn * 64 + nj * 16 + (lane & 15);
                uint32_t o = row * ROWB + ks * 32 + ((lane >> 4) << 4);
                ldsm_x4(bfh[nj], bH + o);
                ldsm_x4(bfl[nj], bL + o);
            }
#pragma unroll
            for (int mi = 0; mi < 2; mi++)
#pragma unroll
                for (int nj = 0; nj < 8; nj++) {
                    uint32_t bh0 = bfh[nj >> 1][nj & 1], bh1 = bfh[nj >> 1][2 + (nj & 1)];
                    uint32_t bl0 = bfl[nj >> 1][nj & 1], bl1 = bfl[nj >> 1][2 + (nj & 1)];
                    mma16816(acc[mi][nj], afh[mi], bh0, bh1);   // hi*hi
                    mma16816(acc[mi][nj], afl[mi], bh0, bh1);   // lo*hi
                    mma16816(acc[mi][nj], afh[mi], bl0, bl1);   // hi*lo
                }
        }
        __syncthreads();
    }

    // epilogue
    const int gid = lane >> 2, tig = lane & 3;
#pragma unroll
    for (int mi = 0; mi < 2; mi++) {
        int mrow = m0 + wm * 32 + mi * 16 + gid;
#pragma unroll
        for (int nj = 0; nj < 8; nj++) {
            int col = n0 + wn * 64 + nj * 8 + tig * 2;
            if (mrow < NN)
                *(float2*)(g_wq + (size_t)mrow * TWO_D + col) =
                    make_float2(acc[mi][nj][0], acc[mi][nj][1]);
            if (mrow + 8 < NN)
                *(float2*)(g_wq + (size_t)(mrow + 8) * TWO_D + col) =
                    make_float2(acc[mi][nj][2], acc[mi][nj][3]);
        }
    }
}

// ---------------------------------------------------------------------------
// Edge attention: two independent online-softmax chains (unchanged from R5).
// ---------------------------------------------------------------------------
__global__ __launch_bounds__(256) void edge_attn(const float* __restrict__ v_fea,
                                                 const float* __restrict__ t_emb,
                                                 const int* __restrict__ ef,
                                                 float* __restrict__ out) {
    const int warp = (blockIdx.x * blockDim.x + threadIdx.x) >> 5;
    const int lane = threadIdx.x & 31;
    if (warp >= NN) return;

    const float* wqr = g_wq + (size_t)warp * TWO_D;
    const float4 wqa = *(const float4*)(wqr + lane * 4);
    const float4 wqb = *(const float4*)(wqr + DD + lane * 4);

    const int e_mine = ef[(size_t)warp * KK + lane];

    float m1 = -INFINITY, s1 = 0.f;
    float m2 = -INFINITY, s2 = 0.f;
    float4 a1 = make_float4(0.f, 0.f, 0.f, 0.f);
    float4 a2 = make_float4(0.f, 0.f, 0.f, 0.f);

#pragma unroll 2
    for (int k = 0; k < KK; k += 2) {
        int e1 = __shfl_sync(0xffffffffu, e_mine, k);
        int e2 = __shfl_sync(0xffffffffu, e_mine, k + 1);
        const float4 v1 = *(const float4*)(v_fea + (size_t)e1 * DD + lane * 4);
        const float4 t1 = *(const float4*)(t_emb + (size_t)e1 * DD + lane * 4);
        const float4 v2 = *(const float4*)(v_fea + (size_t)e2 * DD + lane * 4);
        const float4 t2 = *(const float4*)(t_emb + (size_t)e2 * DD + lane * 4);

        float p1 = v1.x * wqa.x + v1.y * wqa.y + v1.z * wqa.z + v1.w * wqa.w
                 + t1.x * wqb.x + t1.y * wqb.y + t1.z * wqb.z + t1.w * wqb.w;
        float p2 = v2.x * wqa.x + v2.y * wqa.y + v2.z * wqa.z + v2.w * wqa.w
                 + t2.x * wqb.x + t2.y * wqb.y + t2.z * wqb.z + t2.w * wqb.w;
        p1 += __shfl_xor_sync(0xffffffffu, p1, 16);
        p2 += __shfl_xor_sync(0xffffffffu, p2, 16);
        p1 += __shfl_xor_sync(0xffffffffu, p1, 8);
        p2 += __shfl_xor_sync(0xffffffffu, p2, 8);
        p1 += __shfl_xor_sync(0xffffffffu, p1, 4);
        p2 += __shfl_xor_sync(0xffffffffu, p2, 4);
        p1 += __shfl_xor_sync(0xffffffffu, p1, 2);
        p2 += __shfl_xor_sync(0xffffffffu, p2, 2);
        p1 += __shfl_xor_sync(0xffffffffu, p1, 1);
        p2 += __shfl_xor_sync(0xffffffffu, p2, 1);

        float mn1 = fmaxf(m1, p1);
        float c1 = __expf(m1 - mn1);
        float w1 = __expf(p1 - mn1);
        s1 = s1 * c1 + w1;
        a1.x = a1.x * c1 + w1 * v1.x;
        a1.y = a1.y * c1 + w1 * v1.y;
        a1.z = a1.z * c1 + w1 * v1.z;
        a1.w = a1.w * c1 + w1 * v1.w;
        m1 = mn1;

        float mn2 = fmaxf(m2, p2);
        float c2 = __expf(m2 - mn2);
        float w2 = __expf(p2 - mn2);
        s2 = s2 * c2 + w2;
        a2.x = a2.x * c2 + w2 * v2.x;
        a2.y = a2.y * c2 + w2 * v2.y;
        a2.z = a2.z * c2 + w2 * v2.z;
        a2.w = a2.w * c2 + w2 * v2.w;
        m2 = mn2;
    }

    float mn = fmaxf(m1, m2);
    float c1 = __expf(m1 - mn), c2 = __expf(m2 - mn);
    float s = s1 * c1 + s2 * c2;
    const float inv = 1.f / s;
    float4 o;
    o.x = (a1.x * c1 + a2.x * c2) * inv;
    o.y = (a1.y * c1 + a2.y * c2) * inv;
    o.z = (a1.z * c1 + a2.z * c2) * inv;
    o.w = (a1.w * c1 + a2.w * c2) * inv;
    *(float4*)(out + (size_t)warp * DD + lane * 4) = o;
}

// ---------------------------------------------------------------------------
extern "C" void kernel_launch(void* const* d_in, const int* in_sizes, int n_in,
                              void* d_out, int out_size) {
    const float* v_fea = (const float*)d_in[0];
    const float* t_emb = (const float*)d_in[1];
    const int* ef = (const int*)d_in[2];
    const float* W = (const float*)d_in[3];
    float* out = (float*)d_out;

    cudaFuncSetAttribute(wq_gemm_fused, cudaFuncAttributeMaxDynamicSharedMemorySize, GEMM_SMEM);

    wq_gemm_fused<<<dim3(MP / 128, TWO_D / 128), 256, GEMM_SMEM>>>(v_fea, t_emb, W);

    int grid2 = (NN + 7) / 8;
    edge_attn<<<grid2, 256>>>(v_fea, t_emb, ef, out);
}

// round 7
// speedup vs baseline: 1.5711x; 1.1447x over previous
#include <cuda_runtime.h>
#include <cuda_fp16.h>
#include <math.h>
#include <stdint.h>

#define NN 50000
#define MP 50048          // NN padded to 128
#define DD 128
#define KK 32
#define TWO_D 256

// ---------------------------------------------------------------------------
// Global scratch
// ---------------------------------------------------------------------------
__device__ float g_wq[(size_t)NN * TWO_D];                  // wq = [v|t] @ W.T

// ---------------------------------------------------------------------------
// helpers
// ---------------------------------------------------------------------------
__device__ __forceinline__ uint32_t smem_u32(const void* p) {
    uint32_t a;
    asm("{ .reg .u64 t; cvta.to.shared.u64 t, %1; cvt.u32.u64 %0, t; }" : "=r"(a) : "l"(p));
    return a;
}
__device__ __forceinline__ void ldsm_x4(uint32_t* r, uint32_t addr) {
    asm volatile("ldmatrix.sync.aligned.m8n8.x4.shared.b16 {%0,%1,%2,%3}, [%4];"
                 : "=r"(r[0]), "=r"(r[1]), "=r"(r[2]), "=r"(r[3]) : "r"(addr));
}
__device__ __forceinline__ void mma16816h(float* d, const uint32_t* a, uint32_t b0, uint32_t b1) {
    asm volatile(
        "mma.sync.aligned.m16n8k16.row.col.f32.f16.f16.f32 "
        "{%0,%1,%2,%3}, {%4,%5,%6,%7}, {%8,%9}, {%0,%1,%2,%3};"
        : "+f"(d[0]), "+f"(d[1]), "+f"(d[2]), "+f"(d[3])
        : "r"(a[0]), "r"(a[1]), "r"(a[2]), "r"(a[3]), "r"(b0), "r"(b1));
}
// cp.async with src-size (0 => zero-fill destination)
__device__ __forceinline__ void cp16z(uint32_t saddr, const void* gaddr, uint32_t sz) {
    asm volatile("cp.async.cg.shared.global [%0], [%1], 16, %2;"
                 :: "r"(saddr), "l"(gaddr), "r"(sz));
}
__device__ __forceinline__ void cp_commit() {
    asm volatile("cp.async.commit_group;" ::: "memory");
}

// ---------------------------------------------------------------------------
// Fused GEMM: g_wq[m][j] = sum_k A[m][k] * W[j][k], A = [v_fea | t_emb] fp32.
// BM=128, BN=64. 8 k-chunks of 32. Per chunk: cp.async fp32 chunks, in-kernel
// convert:  A -> single fp16,  W -> fp16 hi/lo.  2 accumulating HMMA passes:
//   A*Whi + A*Wlo    (error only from fp16(A) quantization, ~1.4e-4 rel)
// ---------------------------------------------------------------------------
#define ROWF 144                      // fp32 staging row: 128B + 16B pad
#define STGA_SZ (128 * ROWF)          // 18432
#define STGB_SZ (64 * ROWF)           // 9216
#define ROWB 80                       // fp16 row: 64B + 16B pad
#define ABUF_SZ (128 * ROWB)          // 10240
#define WBUF_SZ (64 * ROWB)           // 5120
// smem: stgA[2] @ 0; stgB[2] @ 36864; f16 stage s @ 55296 + s*20480:
//       {Af16:0, Whi:10240, Wlo:15360}
#define STGB_OFF 36864
#define BF_BASE 55296
#define STAGE_F16 (ABUF_SZ + 2 * WBUF_SZ)      // 20480
#define GEMM_SMEM (BF_BASE + 2 * STAGE_F16)    // 96256

__device__ __forceinline__ void load_chunk(uint32_t sbase, int c, int m0, int n0,
                                           const float* __restrict__ v_fea,
                                           const float* __restrict__ t_emb,
                                           const float* __restrict__ W, int tid) {
    const uint32_t stgA = sbase + (c & 1) * STGA_SZ;
    const uint32_t stgB = sbase + STGB_OFF + (c & 1) * STGB_SZ;
    const float* asrc = (c < 4) ? v_fea : t_emb;
    const int col0 = (c & 3) * 32;
    // A: 128 rows x 8 segs of 16B
#pragma unroll
    for (int g = 0; g < 4; g++) {
        int idx = g * 256 + tid;
        int row = idx >> 3, seg = idx & 7;
        uint32_t szA = (m0 + row < NN) ? 16u : 0u;
        cp16z(stgA + row * ROWF + seg * 16,
              asrc + (size_t)(m0 + row) * DD + col0 + seg * 4, szA);
    }
    // W: 64 rows x 8 segs
#pragma unroll
    for (int g = 0; g < 2; g++) {
        int idx = g * 256 + tid;
        int row = idx >> 3, seg = idx & 7;
        cp16z(stgB + row * ROWF + seg * 16,
              W + (size_t)(n0 + row) * TWO_D + c * 32 + seg * 4, 16u);
    }
    cp_commit();
}

__device__ __forceinline__ void convert_chunk(char* smemc, int c, int tid) {
    const int s = c & 1;
    char* af = smemc + BF_BASE + s * STAGE_F16;
    char* wh = af + ABUF_SZ;
    char* wl = wh + WBUF_SZ;
    // A: 128x32 floats -> fp16. thread: row=tid>>1, 16 cols
    {
        const char* stg = smemc + s * STGA_SZ;
        const int row = tid >> 1;
        const int c0 = (tid & 1) * 16;
#pragma unroll
        for (int i = 0; i < 4; i++) {
            const int cc = c0 + i * 4;
            float4 x = *(const float4*)(stg + row * ROWF + cc * 4);
            __half2 h01 = __floats2half2_rn(x.x, x.y);
            __half2 h23 = __floats2half2_rn(x.z, x.w);
            *(uint2*)(af + row * ROWB + cc * 2) =
                make_uint2(*(uint32_t*)&h01, *(uint32_t*)&h23);
        }
    }
    // W: 64x32 floats -> fp16 hi/lo. thread: row=tid>>2, 8 cols
    {
        const char* stg = smemc + STGB_OFF + s * STGB_SZ;
        const int row = tid >> 2;
        const int c0 = (tid & 3) * 8;
#pragma unroll
        for (int i = 0; i < 2; i++) {
            const int cc = c0 + i * 4;
            float4 x = *(const float4*)(stg + row * ROWF + cc * 4);
            __half2 h01 = __floats2half2_rn(x.x, x.y);
            __half2 h23 = __floats2half2_rn(x.z, x.w);
            float l0 = x.x - __half2float(__low2half(h01));
            float l1 = x.y - __half2float(__high2half(h01));
            float l2 = x.z - __half2float(__low2half(h23));
            float l3 = x.w - __half2float(__high2half(h23));
            __half2 g01 = __floats2half2_rn(l0, l1);
            __half2 g23 = __floats2half2_rn(l2, l3);
            *(uint2*)(wh + row * ROWB + cc * 2) =
                make_uint2(*(uint32_t*)&h01, *(uint32_t*)&h23);
            *(uint2*)(wl + row * ROWB + cc * 2) =
                make_uint2(*(uint32_t*)&g01, *(uint32_t*)&g23);
        }
    }
}

__global__ void __launch_bounds__(256, 2) wq_gemm_fused(const float* __restrict__ v_fea,
                                                        const float* __restrict__ t_emb,
                                                        const float* __restrict__ W) {
    extern __shared__ char smem[];
    const uint32_t sbase = smem_u32(smem);
    const int tid = threadIdx.x;
    const int lane = tid & 31, w = tid >> 5;
    const int wm = w >> 1, wn = w & 1;
    const int m0 = blockIdx.x * 128;
    const int n0 = blockIdx.y * 64;

    float acc[2][4][4];
#pragma unroll
    for (int i = 0; i < 2; i++)
#pragma unroll
        for (int j = 0; j < 4; j++)
#pragma unroll
            for (int q = 0; q < 4; q++) acc[i][j][q] = 0.f;

    // prologue
    load_chunk(sbase, 0, m0, n0, v_fea, t_emb, W, tid);
    load_chunk(sbase, 1, m0, n0, v_fea, t_emb, W, tid);
    asm volatile("cp.async.wait_group 1;" ::: "memory");
    __syncthreads();
    convert_chunk(smem, 0, tid);
    __syncthreads();

    for (int c = 0; c < 8; c++) {
        if (c + 1 < 8) {
            asm volatile("cp.async.wait_group 0;" ::: "memory");
            __syncthreads();
            convert_chunk(smem, c + 1, tid);
            if (c + 2 < 8)
                load_chunk(sbase, c + 2, m0, n0, v_fea, t_emb, W, tid);
        }

        const uint32_t aF = sbase + BF_BASE + (c & 1) * STAGE_F16;
        const uint32_t bH = aF + ABUF_SZ;
        const uint32_t bL = bH + WBUF_SZ;

#pragma unroll
        for (int ks = 0; ks < 2; ks++) {
            uint32_t afr[2][4], bfh[2][4], bfl[2][4];
#pragma unroll
            for (int mi = 0; mi < 2; mi++) {
                int row = wm * 32 + mi * 16 + (lane & 15);
                uint32_t o = row * ROWB + ks * 32 + ((lane >> 4) << 4);
                ldsm_x4(afr[mi], aF + o);
            }
#pragma unroll
            for (int nj2 = 0; nj2 < 2; nj2++) {
                int row = wn * 32 + nj2 * 16 + (lane & 15);
                uint32_t o = row * ROWB + ks * 32 + ((lane >> 4) << 4);
                ldsm_x4(bfh[nj2], bH + o);
                ldsm_x4(bfl[nj2], bL + o);
            }
#pragma unroll
            for (int mi = 0; mi < 2; mi++)
#pragma unroll
                for (int nj = 0; nj < 4; nj++) {
                    uint32_t bh0 = bfh[nj >> 1][nj & 1], bh1 = bfh[nj >> 1][2 + (nj & 1)];
                    uint32_t bl0 = bfl[nj >> 1][nj & 1], bl1 = bfl[nj >> 1][2 + (nj & 1)];
                    mma16816h(acc[mi][nj], afr[mi], bh0, bh1);   // A * Whi
                    mma16816h(acc[mi][nj], afr[mi], bl0, bl1);   // A * Wlo
                }
        }
        __syncthreads();
    }

    // epilogue
    const int gid = lane >> 2, tig = lane & 3;
#pragma unroll
    for (int mi = 0; mi < 2; mi++) {
        int mrow = m0 + wm * 32 + mi * 16 + gid;
#pragma unroll
        for (int nj = 0; nj < 4; nj++) {
            int col = n0 + wn * 32 + nj * 8 + tig * 2;
            if (mrow < NN)
                *(float2*)(g_wq + (size_t)mrow * TWO_D + col) =
                    make_float2(acc[mi][nj][0], acc[mi][nj][1]);
            if (mrow + 8 < NN)
                *(float2*)(g_wq + (size_t)(mrow + 8) * TWO_D + col) =
                    make_float2(acc[mi][nj][2], acc[mi][nj][3]);
        }
    }
}

// ---------------------------------------------------------------------------
// Edge attention: two independent online-softmax chains (unchanged).
// ---------------------------------------------------------------------------
__global__ __launch_bounds__(256) void edge_attn(const float* __restrict__ v_fea,
                                                 const float* __restrict__ t_emb,
                                                 const int* __restrict__ ef,
                                                 float* __restrict__ out) {
    const int warp = (blockIdx.x * blockDim.x + threadIdx.x) >> 5;
    const int lane = threadIdx.x & 31;
    if (warp >= NN) return;

    const float* wqr = g_wq + (size_t)warp * TWO_D;
    const float4 wqa = *(const float4*)(wqr + lane * 4);
    const float4 wqb = *(const float4*)(wqr + DD + lane * 4);

    const int e_mine = ef[(size_t)warp * KK + lane];

    float m1 = -INFINITY, s1 = 0.f;
    float m2 = -INFINITY, s2 = 0.f;
    float4 a1 = make_float4(0.f, 0.f, 0.f, 0.f);
    float4 a2 = make_float4(0.f, 0.f, 0.f, 0.f);

#pragma unroll 2
    for (int k = 0; k < KK; k += 2) {
        int e1 = __shfl_sync(0xffffffffu, e_mine, k);
        int e2 = __shfl_sync(0xffffffffu, e_mine, k + 1);
        const float4 v1 = *(const float4*)(v_fea + (size_t)e1 * DD + lane * 4);
        const float4 t1 = *(const float4*)(t_emb + (size_t)e1 * DD + lane * 4);
        const float4 v2 = *(const float4*)(v_fea + (size_t)e2 * DD + lane * 4);
        const float4 t2 = *(const float4*)(t_emb + (size_t)e2 * DD + lane * 4);

        float p1 = v1.x * wqa.x + v1.y * wqa.y + v1.z * wqa.z + v1.w * wqa.w
                 + t1.x * wqb.x + t1.y * wqb.y + t1.z * wqb.z + t1.w * wqb.w;
        float p2 = v2.x * wqa.x + v2.y * wqa.y + v2.z * wqa.z + v2.w * wqa.w
                 + t2.x * wqb.x + t2.y * wqb.y + t2.z * wqb.z + t2.w * wqb.w;
        p1 += __shfl_xor_sync(0xffffffffu, p1, 16);
        p2 += __shfl_xor_sync(0xffffffffu, p2, 16);
        p1 += __shfl_xor_sync(0xffffffffu, p1, 8);
        p2 += __shfl_xor_sync(0xffffffffu, p2, 8);
        p1 += __shfl_xor_sync(0xffffffffu, p1, 4);
        p2 += __shfl_xor_sync(0xffffffffu, p2, 4);
        p1 += __shfl_xor_sync(0xffffffffu, p1, 2);
        p2 += __shfl_xor_sync(0xffffffffu, p2, 2);
        p1 += __shfl_xor_sync(0xffffffffu, p1, 1);
        p2 += __shfl_xor_sync(0xffffffffu, p2, 1);

        float mn1 = fmaxf(m1, p1);
        float c1 = __expf(m1 - mn1);
        float w1 = __expf(p1 - mn1);
        s1 = s1 * c1 + w1;
        a1.x = a1.x * c1 + w1 * v1.x;
        a1.y = a1.y * c1 + w1 * v1.y;
        a1.z = a1.z * c1 + w1 * v1.z;
        a1.w = a1.w * c1 + w1 * v1.w;
        m1 = mn1;

        float mn2 = fmaxf(m2, p2);
        float c2 = __expf(m2 - mn2);
        float w2 = __expf(p2 - mn2);
        s2 = s2 * c2 + w2;
        a2.x = a2.x * c2 + w2 * v2.x;
        a2.y = a2.y * c2 + w2 * v2.y;
        a2.z = a2.z * c2 + w2 * v2.z;
        a2.w = a2.w * c2 + w2 * v2.w;
        m2 = mn2;
    }

    float mn = fmaxf(m1, m2);
    float c1 = __expf(m1 - mn), c2 = __expf(m2 - mn);
    float s = s1 * c1 + s2 * c2;
    const float inv = 1.f / s;
    float4 o;
    o.x = (a1.x * c1 + a2.x * c2) * inv;
    o.y = (a1.y * c1 + a2.y * c2) * inv;
    o.z = (a1.z * c1 + a2.z * c2) * inv;
    o.w = (a1.w * c1 + a2.w * c2) * inv;
    *(float4*)(out + (size_t)warp * DD + lane * 4) = o;
}

// ---------------------------------------------------------------------------
extern "C" void kernel_launch(void* const* d_in, const int* in_sizes, int n_in,
                              void* d_out, int out_size) {
    const float* v_fea = (const float*)d_in[0];
    const float* t_emb = (const float*)d_in[1];
    const int* ef = (const int*)d_in[2];
    const float* W = (const float*)d_in[3];
    float* out = (float*)d_out;

    cudaFuncSetAttribute(wq_gemm_fused, cudaFuncAttributeMaxDynamicSharedMemorySize, GEMM_SMEM);

    wq_gemm_fused<<<dim3(MP / 128, TWO_D / 64), 256, GEMM_SMEM>>>(v_fea, t_emb, W);

    int grid2 = (NN + 7) / 8;
    edge_attn<<<grid2, 256>>>(v_fea, t_emb, ef, out);
}